// round 1
// baseline (speedup 1.0000x reference)
#include <cuda_runtime.h>
#include <cuda_bf16.h>

// Problem constants: B=8, C=512, H=W=56 -> N=3136, E=256
#define BATCH 8
#define CCH  512
#define NSP  3136
#define EMB  256

// Scratch in __device__ globals (allocation in kernel_launch is forbidden).
__device__ float g_q[(size_t)BATCH * EMB * NSP];     // E x N per batch
__device__ float g_k[(size_t)BATCH * EMB * NSP];     // E x N per batch
__device__ float g_v[(size_t)BATCH * EMB * NSP];     // E x N per batch
__device__ float g_attn[(size_t)BATCH * NSP * NSP];  // N x N per batch
__device__ float g_emb[(size_t)BATCH * NSP * EMB];   // N x E per batch

// ----------------------------------------------------------------------------
// Generic tiled SGEMM:  C[m,n] = alpha * sum_k A(k,m)*B(k,n) (+bias[m]) (+res)
//   AT=true : A stored K x M row-major (element A[k*M+m])
//   AT=false: A stored M x K row-major (element A[m*K+k])
//   BT=false: B stored K x N row-major
//   BT=true : B stored N x K row-major
// 128x128x8 tile, 256 threads, 8x8 per-thread register blocking.
// K must be a multiple of 8 (true for all uses: 512, 256, 3136).
// ----------------------------------------------------------------------------
template<bool AT, bool BT, bool HAS_BIAS, bool HAS_RES>
__global__ __launch_bounds__(256)
void gemm_k(const float* __restrict__ A, const float* __restrict__ B,
            float* __restrict__ Cm,
            const float* __restrict__ bias, const float* __restrict__ resid,
            int M, int N, int K,
            long long sA, long long sB, long long sC, long long sR,
            float alpha)
{
    constexpr int BMv = 128, BNv = 128, BKv = 8;
    __shared__ float As[BKv][BMv + 4];
    __shared__ float Bs[BKv][BNv + 4];

    const int bz = blockIdx.z;
    A  += (long long)bz * sA;
    B  += (long long)bz * sB;
    Cm += (long long)bz * sC;
    const float* Rp = HAS_RES ? (resid + (long long)bz * sR) : nullptr;

    const int bm = blockIdx.y * BMv;
    const int bn = blockIdx.x * BNv;
    const int tid = threadIdx.x;
    const int ty = tid >> 4;      // 0..15
    const int tx = tid & 15;      // 0..15

    float acc[8][8];
#pragma unroll
    for (int i = 0; i < 8; i++)
#pragma unroll
        for (int j = 0; j < 8; j++) acc[i][j] = 0.f;

    // Loader thread mappings
    int a_k, a_m, b_k, b_n;
    if (AT) { a_k = tid >> 5; a_m = (tid & 31) * 4; }   // 8 rows x 128 cols, float4
    else    { a_m = tid >> 1; a_k = (tid & 1) * 4; }    // 128 rows x 8 cols, float4 + transpose
    if (!BT) { b_k = tid >> 5; b_n = (tid & 31) * 4; }
    else     { b_n = tid >> 1; b_k = (tid & 1) * 4; }

    for (int k0 = 0; k0 < K; k0 += BKv) {
        // ---- load A tile ----
        if (AT) {
            int gm = bm + a_m;
            float4 v = make_float4(0.f, 0.f, 0.f, 0.f);
            if (gm < M) v = *(const float4*)&A[(long long)(k0 + a_k) * M + gm];
            *(float4*)&As[a_k][a_m] = v;
        } else {
            int gm = bm + a_m;
            float4 v = make_float4(0.f, 0.f, 0.f, 0.f);
            if (gm < M) v = *(const float4*)&A[(long long)gm * K + (k0 + a_k)];
            As[a_k + 0][a_m] = v.x;
            As[a_k + 1][a_m] = v.y;
            As[a_k + 2][a_m] = v.z;
            As[a_k + 3][a_m] = v.w;
        }
        // ---- load B tile ----
        if (!BT) {
            int gn = bn + b_n;
            float4 v = make_float4(0.f, 0.f, 0.f, 0.f);
            if (gn < N) v = *(const float4*)&B[(long long)(k0 + b_k) * N + gn];
            *(float4*)&Bs[b_k][b_n] = v;
        } else {
            int gn = bn + b_n;
            float4 v = make_float4(0.f, 0.f, 0.f, 0.f);
            if (gn < N) v = *(const float4*)&B[(long long)gn * K + (k0 + b_k)];
            Bs[b_k + 0][b_n] = v.x;
            Bs[b_k + 1][b_n] = v.y;
            Bs[b_k + 2][b_n] = v.z;
            Bs[b_k + 3][b_n] = v.w;
        }
        __syncthreads();

#pragma unroll
        for (int kk = 0; kk < BKv; kk++) {
            float a[8], b[8];
#pragma unroll
            for (int i = 0; i < 8; i++) a[i] = As[kk][ty * 8 + i];
#pragma unroll
            for (int j = 0; j < 8; j++) b[j] = Bs[kk][tx * 8 + j];
#pragma unroll
            for (int i = 0; i < 8; i++)
#pragma unroll
                for (int j = 0; j < 8; j++) acc[i][j] += a[i] * b[j];
        }
        __syncthreads();
    }

    // ---- epilogue ----
#pragma unroll
    for (int i = 0; i < 8; i++) {
        int gm = bm + ty * 8 + i;
        if (gm >= M) continue;
        float bv = HAS_BIAS ? bias[gm] : 0.f;
#pragma unroll
        for (int j = 0; j < 8; j++) {
            int gn = bn + tx * 8 + j;
            if (gn < N) {
                float v = acc[i][j] * alpha + bv;
                if (HAS_RES) v += Rp[(long long)gm * N + gn];
                Cm[(long long)gm * N + gn] = v;
            }
        }
    }
}

extern "C" void kernel_launch(void* const* d_in, const int* in_sizes, int n_in,
                              void* d_out, int out_size)
{
    const float* x  = (const float*)d_in[0];
    const float* wq = (const float*)d_in[1];
    const float* bq = (const float*)d_in[2];
    const float* wk = (const float*)d_in[3];
    const float* bk = (const float*)d_in[4];
    const float* wv = (const float*)d_in[5];
    const float* bv = (const float*)d_in[6];
    const float* wo = (const float*)d_in[7];
    const float* bo = (const float*)d_in[8];
    float* out = (float*)d_out;

    float *q, *k, *v, *attn, *emb;
    cudaGetSymbolAddress((void**)&q,    g_q);
    cudaGetSymbolAddress((void**)&k,    g_k);
    cudaGetSymbolAddress((void**)&v,    g_v);
    cudaGetSymbolAddress((void**)&attn, g_attn);
    cudaGetSymbolAddress((void**)&emb,  g_emb);

    const int Bb = BATCH, Cc = CCH, Nn = NSP, Ee = EMB;
    const long long sX  = (long long)Cc * Nn;   // x batch stride
    const long long sQ  = (long long)Ee * Nn;   // q/k/v batch stride
    const long long sAt = (long long)Nn * Nn;   // attn batch stride
    const long long sE  = (long long)Nn * Ee;   // embed batch stride

    dim3 blk(256);

    // 1-3) Q/K/V = w (ExC, MxK) @ x (CxN, KxN)  + bias      -> ExN     [NN]
    dim3 g1((Nn + 127) / 128, (Ee + 127) / 128, Bb);
    gemm_k<false, false, true, false><<<g1, blk>>>(wq, x, q, bq, nullptr,
        Ee, Nn, Cc, 0, sX, sQ, 0, 1.f);
    gemm_k<false, false, true, false><<<g1, blk>>>(wk, x, k, bk, nullptr,
        Ee, Nn, Cc, 0, sX, sQ, 0, 1.f);
    gemm_k<false, false, true, false><<<g1, blk>>>(wv, x, v, bv, nullptr,
        Ee, Nn, Cc, 0, sX, sQ, 0, 1.f);

    // 4) attn[n,m] = (1/N) * sum_e Q[e,n] K[e,m]            -> NxN     [TN]
    dim3 g2((Nn + 127) / 128, (Nn + 127) / 128, Bb);
    gemm_k<true, false, false, false><<<g2, blk>>>(q, k, attn, nullptr, nullptr,
        Nn, Nn, Ee, sQ, sQ, sAt, 0, 1.f / (float)Nn);

    // 5) emb[n,e] = sum_m attn[n,m] V[e,m]                  -> NxE     [NT]
    dim3 g3((Ee + 127) / 128, (Nn + 127) / 128, Bb);
    gemm_k<false, true, false, false><<<g3, blk>>>(attn, v, emb, nullptr, nullptr,
        Nn, Ee, Nn, sAt, sQ, sE, 0, 1.f);

    // 6) out[c,n] = sum_e wo[c,e] emb[n,e] + bo[c] + x[c,n] -> CxN     [NT + bias + residual]
    dim3 g4((Nn + 127) / 128, (Cc + 127) / 128, Bb);
    gemm_k<false, true, true, true><<<g4, blk>>>(wo, emb, out, bo, x,
        Cc, Nn, Ee, 0, sE, sX, sX, 1.f);
}

// round 2
// speedup vs baseline: 11.9173x; 11.9173x over previous
#include <cuda_runtime.h>
#include <cuda_bf16.h>
#include <cstdint>

// Problem constants: B=8, C=512, H=W=56 -> N=3136, E=256
#define BATCH 8
#define CCH   512
#define NSP   3136
#define EMB   256
#define E3    768

// ---------------- scratch (__device__ globals; no allocation allowed) -------
__device__ __nv_bfloat16 g_wqkv[E3 * CCH];                       // 768x512
__device__ float         g_bqkv[E3];
__device__ __nv_bfloat16 g_wo[CCH * EMB];                       // 512x256
__device__ __nv_bfloat16 g_xT[(size_t)BATCH * NSP * CCH];       // per b: 3136x512 (n-major)
__device__ __nv_bfloat16 g_qkv[(size_t)BATCH * E3 * NSP];       // per b: 768x3136 (e-major)
__device__ __nv_bfloat16 g_qT[(size_t)BATCH * NSP * EMB];       // per b: 3136x256
__device__ __nv_bfloat16 g_a2[(size_t)BATCH * EMB * EMB];       // per b: 256x256  (kv^T: a2[e][f])
__device__ __nv_bfloat16 g_emb[(size_t)BATCH * NSP * EMB];      // per b: 3136x256

__device__ __forceinline__ uint32_t sptr(const void* p) {
    return (uint32_t)__cvta_generic_to_shared(p);
}

// ---------------- layout prep kernels ---------------------------------------
__global__ void pack_w(const float* __restrict__ wq, const float* __restrict__ wk,
                       const float* __restrict__ wv, const float* __restrict__ bq,
                       const float* __restrict__ bk, const float* __restrict__ bv,
                       const float* __restrict__ wo)
{
    int i = blockIdx.x * blockDim.x + threadIdx.x;
    if (i < E3 * CCH) {
        int r = i / CCH, c = i % CCH;
        const float* src = (r < EMB) ? wq : (r < 2 * EMB ? wk : wv);
        g_wqkv[i] = __float2bfloat16(src[(r % EMB) * CCH + c]);
    }
    if (i < CCH * EMB) g_wo[i] = __float2bfloat16(wo[i]);
    if (i < E3) {
        const float* bs = (i < EMB) ? bq : (i < 2 * EMB ? bk : bv);
        g_bqkv[i] = bs[i % EMB];
    }
}

// x [C][N] fp32 -> xT [N][C] bf16 (per batch). grid (N/32, C/32, B), block (32,8)
__global__ void conv_xT(const float* __restrict__ x)
{
    __shared__ float t[32][33];
    int bz = blockIdx.z;
    const float* xb = x + (size_t)bz * CCH * NSP;
    __nv_bfloat16* xt = g_xT + (size_t)bz * NSP * CCH;
    int n0 = blockIdx.x * 32, c0 = blockIdx.y * 32;
#pragma unroll
    for (int i = threadIdx.y; i < 32; i += 8)
        t[i][threadIdx.x] = xb[(size_t)(c0 + i) * NSP + n0 + threadIdx.x];
    __syncthreads();
#pragma unroll
    for (int i = threadIdx.y; i < 32; i += 8)
        xt[(size_t)(n0 + i) * CCH + c0 + threadIdx.x] = __float2bfloat16(t[threadIdx.x][i]);
}

// Q (rows 0..255 of qkv [768][N]) -> qT [N][256] bf16. grid (N/32, E/32, B), block (32,8)
__global__ void trans_qT()
{
    __shared__ __nv_bfloat16 t[32][33];
    int bz = blockIdx.z;
    const __nv_bfloat16* q = g_qkv + (size_t)bz * E3 * NSP;   // Q = first 256 rows
    __nv_bfloat16* qt = g_qT + (size_t)bz * NSP * EMB;
    int n0 = blockIdx.x * 32, e0 = blockIdx.y * 32;
#pragma unroll
    for (int i = threadIdx.y; i < 32; i += 8)
        t[i][threadIdx.x] = q[(size_t)(e0 + i) * NSP + n0 + threadIdx.x];
    __syncthreads();
#pragma unroll
    for (int i = threadIdx.y; i < 32; i += 8)
        qt[(size_t)(n0 + i) * EMB + e0 + threadIdx.x] = t[threadIdx.x][i];
}

// ---------------- bf16 NT tensor-core GEMM ----------------------------------
// C[m][n] = alpha * sum_k A[m][k] * B[n][k]  (+bias[m]) (+resid) ; per-z batch
// A: MxK row-major bf16, B: NxK row-major bf16.
// 128x128x32 tile, 256 threads (8 warps, 2x4), warp tile 64x32 via m16n8k16.
#define LDSS 40   // smem row stride in bf16 (32 + 8 pad -> conflict-free ldmatrix)

template<bool BIAS, bool RES, bool OUTF32>
__global__ __launch_bounds__(256)
void gemm_bf(const __nv_bfloat16* __restrict__ A, const __nv_bfloat16* __restrict__ B,
             void* __restrict__ Cptr, const float* __restrict__ bias,
             const float* __restrict__ resid,
             int M, int N, int K,
             long long sA, long long sB, long long sC, long long sR, float alpha)
{
    __shared__ __align__(16) __nv_bfloat16 As[2][128 * LDSS];
    __shared__ __align__(16) __nv_bfloat16 Bs[2][128 * LDSS];

    const int bz = blockIdx.z;
    A += bz * sA;
    B += bz * sB;
    const int bm = blockIdx.y * 128, bn = blockIdx.x * 128;
    const int tid = threadIdx.x, lane = tid & 31, warp = tid >> 5;
    const int wm = (warp >> 2) * 64, wn = (warp & 3) * 32;

    // global->smem loader mapping: each thread copies 2x16B for A and B per stage
    const int lrow = tid >> 2;          // 0..63
    const int lchunk = (tid & 3) * 8;   // bf16 col offset within BK=32

    float acc[4][4][4];
#pragma unroll
    for (int i = 0; i < 4; i++)
#pragma unroll
        for (int j = 0; j < 4; j++)
#pragma unroll
            for (int v = 0; v < 4; v++) acc[i][j][v] = 0.f;

    const int KT = K / 32;

    // ---- stage loader (cp.async, zero-fill OOB rows) ----
#define LOAD_STAGE(ST, K0)                                                          \
    {                                                                               \
        _Pragma("unroll")                                                           \
        for (int it = 0; it < 2; it++) {                                            \
            int r = lrow + it * 64;                                                 \
            {                                                                       \
                int gm = bm + r;                                                    \
                const __nv_bfloat16* src = A + (long long)gm * K + (K0) + lchunk;   \
                uint32_t dst = sptr(&As[ST][r * LDSS + lchunk]);                    \
                int szz = (gm < M) ? 16 : 0;                                        \
                asm volatile("cp.async.cg.shared.global [%0], [%1], 16, %2;\n"      \
                             :: "r"(dst), "l"(src), "r"(szz));                      \
            }                                                                       \
            {                                                                       \
                int gn = bn + r;                                                    \
                const __nv_bfloat16* src = B + (long long)gn * K + (K0) + lchunk;   \
                uint32_t dst = sptr(&Bs[ST][r * LDSS + lchunk]);                    \
                int szz = (gn < N) ? 16 : 0;                                        \
                asm volatile("cp.async.cg.shared.global [%0], [%1], 16, %2;\n"      \
                             :: "r"(dst), "l"(src), "r"(szz));                      \
            }                                                                       \
        }                                                                           \
    }

    LOAD_STAGE(0, 0);
    asm volatile("cp.async.commit_group;\n");

    for (int kt = 0; kt < KT; kt++) {
        if (kt + 1 < KT) { LOAD_STAGE((kt + 1) & 1, (kt + 1) * 32); }
        asm volatile("cp.async.commit_group;\n");
        if (kt + 1 < KT) asm volatile("cp.async.wait_group 1;\n");
        else             asm volatile("cp.async.wait_group 0;\n");
        __syncthreads();

        const __nv_bfloat16* as = As[kt & 1];
        const __nv_bfloat16* bs = Bs[kt & 1];
#pragma unroll
        for (int kk = 0; kk < 2; kk++) {
            uint32_t af[4][4], bfrag[4][2];
#pragma unroll
            for (int i = 0; i < 4; i++) {
                int row = wm + i * 16 + (lane & 15);
                int col = kk * 16 + (lane >> 4) * 8;
                uint32_t addr = sptr(&as[row * LDSS + col]);
                asm volatile("ldmatrix.sync.aligned.m8n8.x4.shared.b16 {%0,%1,%2,%3}, [%4];\n"
                             : "=r"(af[i][0]), "=r"(af[i][1]), "=r"(af[i][2]), "=r"(af[i][3])
                             : "r"(addr));
            }
#pragma unroll
            for (int j = 0; j < 4; j++) {
                int nrow = wn + j * 8 + (lane & 7);
                int col = kk * 16 + ((lane >> 3) & 1) * 8;
                uint32_t addr = sptr(&bs[nrow * LDSS + col]);
                asm volatile("ldmatrix.sync.aligned.m8n8.x2.shared.b16 {%0,%1}, [%2];\n"
                             : "=r"(bfrag[j][0]), "=r"(bfrag[j][1]) : "r"(addr));
            }
#pragma unroll
            for (int i = 0; i < 4; i++)
#pragma unroll
                for (int j = 0; j < 4; j++) {
                    asm volatile(
                        "mma.sync.aligned.m16n8k16.row.col.f32.bf16.bf16.f32 "
                        "{%0,%1,%2,%3}, {%4,%5,%6,%7}, {%8,%9}, {%0,%1,%2,%3};\n"
                        : "+f"(acc[i][j][0]), "+f"(acc[i][j][1]),
                          "+f"(acc[i][j][2]), "+f"(acc[i][j][3])
                        : "r"(af[i][0]), "r"(af[i][1]), "r"(af[i][2]), "r"(af[i][3]),
                          "r"(bfrag[j][0]), "r"(bfrag[j][1]));
                }
        }
        __syncthreads();
    }
#undef LOAD_STAGE

    // ---- epilogue ----
    float* Cf = (float*)Cptr + (OUTF32 ? bz * sC : 0);
    __nv_bfloat16* Cb = (__nv_bfloat16*)Cptr + (OUTF32 ? 0 : bz * sC);
    const float* Rp = RES ? (resid + bz * sR) : nullptr;

#pragma unroll
    for (int i = 0; i < 4; i++) {
        int r0 = bm + wm + i * 16 + (lane >> 2);
#pragma unroll
        for (int j = 0; j < 4; j++) {
            int c0 = bn + wn + j * 8 + (lane & 3) * 2;
#pragma unroll
            for (int h = 0; h < 2; h++) {
                int rr = r0 + h * 8;
                if (rr < M && c0 < N) {
                    float v0 = acc[i][j][2 * h] * alpha;
                    float v1 = acc[i][j][2 * h + 1] * alpha;
                    if (BIAS) { float bb = bias[rr]; v0 += bb; v1 += bb; }
                    long long idx = (long long)rr * N + c0;
                    if (OUTF32) {
                        if (RES) { v0 += Rp[idx]; v1 += Rp[idx + 1]; }
                        Cf[idx] = v0; Cf[idx + 1] = v1;
                    } else {
                        *(__nv_bfloat162*)&Cb[idx] = __floats2bfloat162_rn(v0, v1);
                    }
                }
            }
        }
    }
}

// ---------------- host launch ------------------------------------------------
extern "C" void kernel_launch(void* const* d_in, const int* in_sizes, int n_in,
                              void* d_out, int out_size)
{
    const float* x  = (const float*)d_in[0];
    const float* wq = (const float*)d_in[1];
    const float* bq = (const float*)d_in[2];
    const float* wk = (const float*)d_in[3];
    const float* bk = (const float*)d_in[4];
    const float* wv = (const float*)d_in[5];
    const float* bv = (const float*)d_in[6];
    const float* wo = (const float*)d_in[7];
    const float* bo = (const float*)d_in[8];
    float* out = (float*)d_out;

    __nv_bfloat16 *qkv, *qT, *a2, *emb, *wqkvp, *wop;
    float* bqkvp;
    cudaGetSymbolAddress((void**)&qkv,   g_qkv);
    cudaGetSymbolAddress((void**)&qT,    g_qT);
    cudaGetSymbolAddress((void**)&a2,    g_a2);
    cudaGetSymbolAddress((void**)&emb,   g_emb);
    cudaGetSymbolAddress((void**)&wqkvp, g_wqkv);
    cudaGetSymbolAddress((void**)&wop,   g_wo);
    cudaGetSymbolAddress((void**)&bqkvp, g_bqkv);
    __nv_bfloat16* xT;
    cudaGetSymbolAddress((void**)&xT, g_xT);

    const long long sX  = (long long)CCH * NSP;    // 512*3136
    const long long sXT = (long long)NSP * CCH;
    const long long sQK = (long long)E3 * NSP;     // 768*3136
    const long long sQT = (long long)NSP * EMB;
    const long long sA2 = (long long)EMB * EMB;
    const long long sEM = (long long)NSP * EMB;

    dim3 blk(256);

    // prep: pack weights + transpose/convert x
    pack_w<<<(E3 * CCH + 255) / 256, 256>>>(wq, wk, wv, bq, bk, bv, wo);
    conv_xT<<<dim3(NSP / 32, CCH / 32, BATCH), dim3(32, 8)>>>(x);

    // GEMM1: qkv[e'][n] = wqkv[e'][c] . xT[n][c] + b   (M=768,N=3136,K=512)
    gemm_bf<true, false, false><<<dim3((NSP + 127) / 128, E3 / 128, BATCH), blk>>>(
        wqkvp, xT, qkv, bqkvp, nullptr, E3, NSP, CCH, 0, sXT, sQK, 0, 1.f);

    // transpose Q -> qT [n][e]
    trans_qT<<<dim3(NSP / 32, EMB / 32, BATCH), dim3(32, 8)>>>();

    // GEMM2: a2[e][f] = V[e][n] . K[f][n]   (M=256,N=256,K=3136)
    gemm_bf<false, false, false><<<dim3(2, 2, BATCH), blk>>>(
        qkv + (long long)2 * EMB * NSP, qkv + (long long)EMB * NSP, a2,
        nullptr, nullptr, EMB, EMB, NSP, sQK, sQK, sA2, 0, 1.f);

    // GEMM3: emb[n][e] = (1/N) * qT[n][f] . a2[e][f]   (M=3136,N=256,K=256)
    gemm_bf<false, false, false><<<dim3(EMB / 128, (NSP + 127) / 128, BATCH), blk>>>(
        qT, a2, emb, nullptr, nullptr, NSP, EMB, EMB, sQT, sA2, sEM, 0,
        1.f / (float)NSP);

    // GEMM4: out[c][n] = wo[c][e] . emb[n][e] + bo[c] + x[c][n]  (M=512,N=3136,K=256)
    gemm_bf<true, true, true><<<dim3((NSP + 127) / 128, CCH / 128, BATCH), blk>>>(
        wop, emb, out, bo, x, CCH, NSP, EMB, 0, sEM, sX, sX, 1.f);
}

// round 3
// speedup vs baseline: 15.1560x; 1.2718x over previous
#include <cuda_runtime.h>
#include <cuda_bf16.h>
#include <cstdint>

// Problem constants: B=8, C=512, H=W=56 -> N=3136, E=256
#define BATCH 8
#define CCH   512
#define NSP   3136
#define EMB   256
#define E3    768

// ---------------- scratch (__device__ globals; no allocation allowed) -------
__device__ __nv_bfloat16 g_wqkv[E3 * CCH];                       // 768x512
__device__ float         g_bqkv[E3];
__device__ __nv_bfloat16 g_wo[CCH * EMB];                        // 512x256
__device__ __nv_bfloat16 g_xb[(size_t)BATCH * CCH * NSP];        // per b: 512x3136 (c-major, like x)
__device__ __nv_bfloat16 g_qkv[(size_t)BATCH * E3 * NSP];        // per b: 768x3136 (e-major)
__device__ __nv_bfloat16 g_a2[(size_t)BATCH * EMB * EMB];        // per b: 256x256 (kv^T)
__device__ __nv_bfloat16 g_embT[(size_t)BATCH * EMB * NSP];      // per b: 256x3136 (e-major)

__device__ __forceinline__ uint32_t sptr(const void* p) {
    return (uint32_t)__cvta_generic_to_shared(p);
}

// ---------------- layout prep kernels ---------------------------------------
__global__ void pack_w(const float* __restrict__ wq, const float* __restrict__ wk,
                       const float* __restrict__ wv, const float* __restrict__ bq,
                       const float* __restrict__ bk, const float* __restrict__ bv,
                       const float* __restrict__ wo)
{
    int i = blockIdx.x * blockDim.x + threadIdx.x;
    if (i < E3 * CCH) {
        int r = i / CCH, c = i % CCH;
        const float* src = (r < EMB) ? wq : (r < 2 * EMB ? wk : wv);
        g_wqkv[i] = __float2bfloat16(src[(r % EMB) * CCH + c]);
    }
    if (i < CCH * EMB) g_wo[i] = __float2bfloat16(wo[i]);
    if (i < E3) {
        const float* bs = (i < EMB) ? bq : (i < 2 * EMB ? bk : bv);
        g_bqkv[i] = bs[i % EMB];
    }
}

// Straight fp32 -> bf16 convert of x (no transpose). Vectorized 4-wide.
__global__ void conv_xb(const float* __restrict__ x, long long total4)
{
    long long i = (long long)blockIdx.x * blockDim.x + threadIdx.x;
    if (i >= total4) return;
    float4 v = ((const float4*)x)[i];
    __nv_bfloat162 lo = __floats2bfloat162_rn(v.x, v.y);
    __nv_bfloat162 hi = __floats2bfloat162_rn(v.z, v.w);
    ((__nv_bfloat162*)g_xb)[2 * i]     = lo;
    ((__nv_bfloat162*)g_xb)[2 * i + 1] = hi;
}

// ---------------- bf16 tensor-core GEMM (NT or NN B operand) -----------------
// C[m][n] = alpha * sum_k A[m][k]*B(k,n) (+bias[m]) (+resid) ; per-z batch
//   A: MxK row-major bf16 (always)
//   BNMAJ=false (NT): B is NxK row-major
//   BNMAJ=true  (NN): B is KxN row-major
// Tile BMxBNx32, warps (WGM x WGN), warp tile (BM/WGM x BN/WGN), m16n8k16.
// K must be a multiple of 32. N must be a multiple of 8.
#define LDSS 40   // A / NT-B smem row stride (32 + 8 pad)

template<int BM, int BN, int WGM, int WGN, bool BNMAJ, bool BIAS, bool RES, bool OUTF32>
__global__ __launch_bounds__(WGM * WGN * 32)
void gemm_bf(const __nv_bfloat16* __restrict__ A, const __nv_bfloat16* __restrict__ B,
             void* __restrict__ Cptr, const float* __restrict__ bias,
             const float* __restrict__ resid,
             int M, int N, int K,
             long long sA, long long sB, long long sC, long long sR, float alpha)
{
    constexpr int T    = WGM * WGN * 32;
    constexpr int WM   = BM / WGM;
    constexpr int WN   = BN / WGN;
    constexpr int MI   = WM / 16;
    constexpr int NJ   = WN / 8;
    constexpr int LDBN = BN + 8;                 // NN B smem row stride

    __shared__ __align__(16) __nv_bfloat16 As[2][BM * LDSS];
    __shared__ __align__(16) __nv_bfloat16 Bs[2][BNMAJ ? 32 * LDBN : BN * LDSS];

    const int bz = blockIdx.z;
    A += bz * sA;
    B += bz * sB;
    const int bm = blockIdx.y * BM, bn = blockIdx.x * BN;
    const int tid = threadIdx.x, lane = tid & 31, warp = tid >> 5;
    const int wm = (warp / WGN) * WM, wn = (warp % WGN) * WN;

    float acc[MI][NJ][4];
#pragma unroll
    for (int i = 0; i < MI; i++)
#pragma unroll
        for (int j = 0; j < NJ; j++)
#pragma unroll
            for (int v = 0; v < 4; v++) acc[i][j][v] = 0.f;

    const int KT = K / 32;

#define LOAD_STAGE(ST, K0)                                                          \
    {                                                                               \
        _Pragma("unroll")                                                           \
        for (int p = 0; p < BM * 4 / T; p++) {                                      \
            int r  = (tid >> 2) + p * (T / 4);                                      \
            int ck = (tid & 3) * 8;                                                 \
            int gm = bm + r;                                                        \
            const __nv_bfloat16* src = A + (long long)gm * K + (K0) + ck;           \
            uint32_t dst = sptr(&As[ST][r * LDSS + ck]);                            \
            int szz = (gm < M) ? 16 : 0;                                            \
            asm volatile("cp.async.cg.shared.global [%0], [%1], 16, %2;\n"          \
                         :: "r"(dst), "l"(src), "r"(szz));                          \
        }                                                                           \
        if (BNMAJ) {                                                                \
            _Pragma("unroll")                                                       \
            for (int p = 0; p < 32 * (BN / 8) / T; p++) {                           \
                int r  = tid / (BN / 8) + p * (T / (BN / 8));                       \
                int cc = (tid % (BN / 8)) * 8;                                      \
                int gn = bn + cc;                                                   \
                const __nv_bfloat16* src = B + (long long)((K0) + r) * N + gn;      \
                uint32_t dst = sptr(&Bs[ST][r * LDBN + cc]);                        \
                int szz = (gn < N) ? 16 : 0;                                        \
                asm volatile("cp.async.cg.shared.global [%0], [%1], 16, %2;\n"      \
                             :: "r"(dst), "l"(src), "r"(szz));                      \
            }                                                                       \
        } else {                                                                    \
            _Pragma("unroll")                                                       \
            for (int p = 0; p < BN * 4 / T; p++) {                                  \
                int r  = (tid >> 2) + p * (T / 4);                                  \
                int ck = (tid & 3) * 8;                                             \
                int gn = bn + r;                                                    \
                const __nv_bfloat16* src = B + (long long)gn * K + (K0) + ck;       \
                uint32_t dst = sptr(&Bs[ST][r * LDSS + ck]);                        \
                int szz = (gn < N) ? 16 : 0;                                        \
                asm volatile("cp.async.cg.shared.global [%0], [%1], 16, %2;\n"      \
                             :: "r"(dst), "l"(src), "r"(szz));                      \
            }                                                                       \
        }                                                                           \
    }

    LOAD_STAGE(0, 0);
    asm volatile("cp.async.commit_group;\n");

    for (int kt = 0; kt < KT; kt++) {
        if (kt + 1 < KT) { LOAD_STAGE((kt + 1) & 1, (kt + 1) * 32); }
        asm volatile("cp.async.commit_group;\n");
        if (kt + 1 < KT) asm volatile("cp.async.wait_group 1;\n");
        else             asm volatile("cp.async.wait_group 0;\n");
        __syncthreads();

        const __nv_bfloat16* as = As[kt & 1];
        const __nv_bfloat16* bs = Bs[kt & 1];
#pragma unroll
        for (int kk = 0; kk < 2; kk++) {
            uint32_t af[MI][4], bfr[NJ][2];
#pragma unroll
            for (int i = 0; i < MI; i++) {
                int row = wm + i * 16 + (lane & 15);
                int col = kk * 16 + (lane >> 4) * 8;
                uint32_t addr = sptr(&as[row * LDSS + col]);
                asm volatile("ldmatrix.sync.aligned.m8n8.x4.shared.b16 {%0,%1,%2,%3}, [%4];\n"
                             : "=r"(af[i][0]), "=r"(af[i][1]), "=r"(af[i][2]), "=r"(af[i][3])
                             : "r"(addr));
            }
#pragma unroll
            for (int j = 0; j < NJ; j++) {
                if (BNMAJ) {
                    int kb = kk * 16 + (lane & 15);
                    uint32_t addr = sptr(&bs[kb * LDBN + wn + j * 8]);
                    asm volatile("ldmatrix.sync.aligned.m8n8.x2.trans.shared.b16 {%0,%1}, [%2];\n"
                                 : "=r"(bfr[j][0]), "=r"(bfr[j][1]) : "r"(addr));
                } else {
                    int nrow = wn + j * 8 + (lane & 7);
                    int col = kk * 16 + ((lane >> 3) & 1) * 8;
                    uint32_t addr = sptr(&bs[nrow * LDSS + col]);
                    asm volatile("ldmatrix.sync.aligned.m8n8.x2.shared.b16 {%0,%1}, [%2];\n"
                                 : "=r"(bfr[j][0]), "=r"(bfr[j][1]) : "r"(addr));
                }
            }
#pragma unroll
            for (int i = 0; i < MI; i++)
#pragma unroll
                for (int j = 0; j < NJ; j++) {
                    asm volatile(
                        "mma.sync.aligned.m16n8k16.row.col.f32.bf16.bf16.f32 "
                        "{%0,%1,%2,%3}, {%4,%5,%6,%7}, {%8,%9}, {%0,%1,%2,%3};\n"
                        : "+f"(acc[i][j][0]), "+f"(acc[i][j][1]),
                          "+f"(acc[i][j][2]), "+f"(acc[i][j][3])
                        : "r"(af[i][0]), "r"(af[i][1]), "r"(af[i][2]), "r"(af[i][3]),
                          "r"(bfr[j][0]), "r"(bfr[j][1]));
                }
        }
        __syncthreads();
    }
#undef LOAD_STAGE

    // ---- epilogue ----
    float* Cf = (float*)Cptr + (OUTF32 ? bz * sC : 0);
    __nv_bfloat16* Cb = (__nv_bfloat16*)Cptr + (OUTF32 ? 0 : bz * sC);
    const float* Rp = RES ? (resid + bz * sR) : nullptr;

#pragma unroll
    for (int i = 0; i < MI; i++) {
        int r0 = bm + wm + i * 16 + (lane >> 2);
#pragma unroll
        for (int j = 0; j < NJ; j++) {
            int c0 = bn + wn + j * 8 + (lane & 3) * 2;
#pragma unroll
            for (int h = 0; h < 2; h++) {
                int rr = r0 + h * 8;
                if (rr < M && c0 < N) {
                    float v0 = acc[i][j][2 * h] * alpha;
                    float v1 = acc[i][j][2 * h + 1] * alpha;
                    if (BIAS) { float bb = bias[rr]; v0 += bb; v1 += bb; }
                    long long idx = (long long)rr * N + c0;
                    if (OUTF32) {
                        if (RES) { v0 += Rp[idx]; v1 += Rp[idx + 1]; }
                        Cf[idx] = v0; Cf[idx + 1] = v1;
                    } else {
                        *(__nv_bfloat162*)&Cb[idx] = __floats2bfloat162_rn(v0, v1);
                    }
                }
            }
        }
    }
}

// ---------------- host launch ------------------------------------------------
extern "C" void kernel_launch(void* const* d_in, const int* in_sizes, int n_in,
                              void* d_out, int out_size)
{
    const float* x  = (const float*)d_in[0];
    const float* wq = (const float*)d_in[1];
    const float* bq = (const float*)d_in[2];
    const float* wk = (const float*)d_in[3];
    const float* bk = (const float*)d_in[4];
    const float* wv = (const float*)d_in[5];
    const float* bv = (const float*)d_in[6];
    const float* wo = (const float*)d_in[7];
    const float* bo = (const float*)d_in[8];
    float* out = (float*)d_out;

    __nv_bfloat16 *qkv, *a2, *embT, *wqkvp, *wop, *xb;
    float* bqkvp;
    cudaGetSymbolAddress((void**)&qkv,   g_qkv);
    cudaGetSymbolAddress((void**)&a2,    g_a2);
    cudaGetSymbolAddress((void**)&embT,  g_embT);
    cudaGetSymbolAddress((void**)&wqkvp, g_wqkv);
    cudaGetSymbolAddress((void**)&wop,   g_wo);
    cudaGetSymbolAddress((void**)&bqkvp, g_bqkv);
    cudaGetSymbolAddress((void**)&xb,    g_xb);

    const long long sX  = (long long)CCH * NSP;    // 512*3136 (x / xb / out)
    const long long sQK = (long long)E3 * NSP;     // 768*3136
    const long long sA2 = (long long)EMB * EMB;    // 256*256
    const long long sET = (long long)EMB * NSP;    // 256*3136

    // prep: pack weights + convert x to bf16 (same layout)
    pack_w<<<(E3 * CCH + 255) / 256, 256>>>(wq, wk, wv, bq, bk, bv, wo);
    long long total4 = (long long)BATCH * sX / 4;
    conv_xb<<<(unsigned)((total4 + 255) / 256), 256>>>(x, total4);

    // GEMM1 (NN): qkv[e'][n] = wqkv[e'][c] . xb[c][n] + b   (M=768,N=3136,K=512)
    gemm_bf<128, 128, 2, 4, true, true, false, false>
        <<<dim3((NSP + 127) / 128, E3 / 128, BATCH), 256>>>(
        wqkvp, xb, qkv, bqkvp, nullptr, E3, NSP, CCH, 0, sX, sQK, 0, 1.f);

    // GEMM2 (NT, 64x64 tiles): a2[e][f] = V[e][n] . K[f][n]  (M=256,N=256,K=3136)
    gemm_bf<64, 64, 2, 2, false, false, false, false>
        <<<dim3(EMB / 64, EMB / 64, BATCH), 128>>>(
        qkv + (long long)2 * EMB * NSP, qkv + (long long)EMB * NSP, a2,
        nullptr, nullptr, EMB, EMB, NSP, sQK, sQK, sA2, 0, 1.f);

    // GEMM3 (NN): embT[e][n] = (1/N) * a2[e][f] . q[f][n]    (M=256,N=3136,K=256)
    gemm_bf<128, 128, 2, 4, true, false, false, false>
        <<<dim3((NSP + 127) / 128, EMB / 128, BATCH), 256>>>(
        a2, qkv, embT, nullptr, nullptr, EMB, NSP, EMB, sA2, sQK, sET, 0,
        1.f / (float)NSP);

    // GEMM4 (NN): out[c][n] = wo[c][e] . embT[e][n] + bo[c] + x[c][n]
    //             (M=512,N=3136,K=256)
    gemm_bf<128, 128, 2, 4, true, true, true, true>
        <<<dim3((NSP + 127) / 128, CCH / 128, BATCH), 256>>>(
        wop, embT, out, bo, x, CCH, NSP, EMB, 0, sET, sX, sX, 1.f);
}